// round 11
// baseline (speedup 1.0000x reference)
#include <cuda_runtime.h>
#include <cstdint>

// Problem shape (fixed by the dataset)
#define Nn 8
#define Cc 32
#define Hh 512
#define Ww 512
#define HW (Hh * Ww)          // 262144
#define OC 32

// ---------------- device scratch (allocation-free rule) ----------------------
__device__ float    g_blockmax[2048];    // per-block |x| maxima
__device__ float    g_sw;                // weight absmax
// Tensor-path layout (R7-proven): i -> slot=i>>3 (slot=(t*8+g)*4+tg), j=i&7
//   (half=j>>2, nt=j&3); word packs ic=(tg+half*4)*4..+3 for oc=nt*8+g, tap t.
__device__ uint32_t g_qw[9 * 8 * 4 * 8];   // 9216 B
// dp4a-path layout (R5-proven): word[oc*72 + t*8 + j] packs ic j*4..+3.
__device__ uint32_t g_qw2[OC * 72];        // 9216 B

// ---------------- kernel 1: x per-block absmax (+ weight prep in block 0) ----
__global__ void k_absmax(const float4* __restrict__ x, const float* __restrict__ w,
                         int n4) {
    __shared__ float sred[8];
    float m = 0.f;
    for (int i = blockIdx.x * blockDim.x + threadIdx.x; i < n4;
         i += gridDim.x * blockDim.x) {
        float4 v = x[i];
        m = fmaxf(m, fmaxf(fmaxf(fabsf(v.x), fabsf(v.y)),
                           fmaxf(fabsf(v.z), fabsf(v.w))));
    }
    #pragma unroll
    for (int o = 16; o; o >>= 1) m = fmaxf(m, __shfl_xor_sync(~0u, m, o));
    if ((threadIdx.x & 31) == 0) sred[threadIdx.x >> 5] = m;
    __syncthreads();
    if (threadIdx.x == 0) {
        float v = sred[0];
        #pragma unroll
        for (int j = 1; j < 8; j++) v = fmaxf(v, sred[j]);
        g_blockmax[blockIdx.x] = v;
    }

    if (blockIdx.x == 0) {   // weight absmax + quantize into both layouts
        __syncthreads();
        float mw = 0.f;
        for (int i = threadIdx.x; i < 9216; i += 256) mw = fmaxf(mw, fabsf(w[i]));
        #pragma unroll
        for (int o = 16; o; o >>= 1) mw = fmaxf(mw, __shfl_xor_sync(~0u, mw, o));
        if ((threadIdx.x & 31) == 0) sred[threadIdx.x >> 5] = mw;
        __syncthreads();
        __shared__ float s_sw;
        if (threadIdx.x == 0) {
            float v = sred[0];
            #pragma unroll
            for (int j = 1; j < 8; j++) v = fmaxf(v, sred[j]);
            s_sw = v;
            g_sw = v;
        }
        __syncthreads();
        float inv = 127.f / s_sw;
        // tensor layout
        for (int i = threadIdx.x; i < 9 * 8 * 4 * 8; i += 256) {
            int slot = i >> 3, j = i & 7;
            int tg = slot & 3, g = (slot >> 2) & 7, t = slot >> 5;
            int nt = j & 3, half = j >> 2;
            int oc  = nt * 8 + g;
            int ic0 = (tg + half * 4) * 4;
            uint32_t p = 0;
            #pragma unroll
            for (int b = 0; b < 4; b++) {
                int q = __float2int_rn(w[(oc * Cc + ic0 + b) * 9 + t] * inv);
                q = max(-127, min(127, q));
                p |= (uint32_t)(q & 0xFF) << (8 * b);
            }
            g_qw[i] = p;
        }
        // dp4a layout
        for (int i = threadIdx.x; i < OC * 72; i += 256) {
            int oc = i / 72, rem = i % 72, t = rem >> 3, j = rem & 7;
            int ic0 = j * 4;
            uint32_t p = 0;
            #pragma unroll
            for (int b = 0; b < 4; b++) {
                int q = __float2int_rn(w[(oc * Cc + ic0 + b) * 9 + t] * inv);
                q = max(-127, min(127, q));
                p |= (uint32_t)(q & 0xFF) << (8 * b);
            }
            g_qw2[i] = p;
        }
    }
}

// ---------------- kernel 2: fused quantize + dual-pipe int8 3x3 conv ---------
// CTA 256 threads, strip = 128 out px x ROWS rows. Ring: 4 rows x 130 px x 32B.
// Warps 0-3: IMMA on px 0..63 (all 32 oc). Warps 4-7: dp4a on px 64..127
// (thread = 1 px x 16 oc). Loader role shared by all threads.

__device__ __forceinline__ void mma_s8(int* c,
                                       uint32_t a0, uint32_t a1, uint32_t a2, uint32_t a3,
                                       uint32_t b0, uint32_t b1) {
    asm volatile(
        "mma.sync.aligned.m16n8k32.row.col.s32.s8.s8.s32 "
        "{%0,%1,%2,%3}, {%4,%5,%6,%7}, {%8,%9}, {%0,%1,%2,%3};\n"
        : "+r"(c[0]), "+r"(c[1]), "+r"(c[2]), "+r"(c[3])
        : "r"(a0), "r"(a1), "r"(a2), "r"(a3), "r"(b0), "r"(b1));
}

#define ROWS 16
#define RSTRIDE 4160   // 130 px * 32 B

// Prologue row fill (load + quant + store).
// Ring row covers px 0..129 <-> w = w0-1 .. w0+128.
__device__ __forceinline__ void load_row_full(char* dst, const float* __restrict__ xn,
                                              int r, int w0, float inv) {
    const int tid = threadIdx.x;
    const bool vr = ((unsigned)r < (unsigned)Hh);
    {   // main: px 0..127, two 16-ch halves
        const int px = tid >> 1, half = tid & 1;
        const int w = w0 - 1 + px;
        const bool vw = vr && ((unsigned)w < (unsigned)Ww);
        const float* p = xn + (size_t)(half * 16) * HW
                       + (size_t)(vw ? r : 0) * Ww + (vw ? w : 0);
        uint32_t wd[4];
        #pragma unroll
        for (int q4 = 0; q4 < 4; q4++) {
            uint32_t pw = 0;
            #pragma unroll
            for (int b = 0; b < 4; b++) {
                float v = vw ? __ldg(p + (size_t)(q4 * 4 + b) * HW) : 0.f;
                int q = max(-127, min(127, __float2int_rn(v * inv)));
                pw |= (uint32_t)(q & 0xFF) << (8 * b);
            }
            wd[q4] = pw;
        }
        *(uint4*)(dst + px * 32 + half * 16) = make_uint4(wd[0], wd[1], wd[2], wd[3]);
    }
    if (tid < 64) {  // px 128,129: one channel per thread
        const int px = 128 + (tid >> 5), ch = tid & 31;
        const int w = w0 - 1 + px;
        float v = 0.f;
        if (vr && (unsigned)w < (unsigned)Ww)
            v = __ldg(xn + (size_t)ch * HW + (size_t)r * Ww + w);
        int q = max(-127, min(127, __float2int_rn(v * inv)));
        *(int8_t*)(dst + px * 32 + ch) = (int8_t)q;
    }
}

__global__ void __launch_bounds__(256) k_conv(const float* __restrict__ x,
                                              float* __restrict__ out,
                                              const float* __restrict__ bias) {
    __shared__ uint32_t s_w[9 * 8 * 4 * 12];  // tensor weights, 48B slots (13824 B)
    __shared__ uint32_t s_w2[OC * 72];        // dp4a weights (9216 B)
    __shared__ char     s_a[4 * RSTRIDE];     // 16640 B ring
    __shared__ float    s_red[8];
    __shared__ float    s_bias[OC];
    __shared__ float    s_scale, s_inv;

    const int tid  = threadIdx.x;
    const int warp = tid >> 5, lane = tid & 31;
    const int n  = blockIdx.z;
    const int h0 = blockIdx.y * ROWS;
    const int w0 = blockIdx.x * 128;
    const float* xn = x + (size_t)n * Cc * HW;

    // final absmax from per-block maxima
    {
        float m = 0.f;
        for (int j = tid; j < 2048; j += 256) m = fmaxf(m, g_blockmax[j]);
        #pragma unroll
        for (int o = 16; o; o >>= 1) m = fmaxf(m, __shfl_xor_sync(~0u, m, o));
        if (lane == 0) s_red[warp] = m;
    }
    if (tid < 32) s_bias[tid] = __ldg(bias + tid);
    __syncthreads();
    if (tid == 0) {
        float v = s_red[0];
        #pragma unroll
        for (int j = 1; j < 8; j++) v = fmaxf(v, s_red[j]);
        s_scale = v * g_sw * (1.f / 16129.f);
        s_inv   = 127.f / v;
    }
    __syncthreads();
    const float inv = s_inv, sc = s_scale;

    // weights -> smem (both layouts); prologue rows -> bufs 0,1,2
    for (int i = tid; i < 9 * 8 * 4 * 8; i += 256)
        s_w[(i >> 3) * 12 + (i & 7)] = g_qw[i];
    for (int i = tid; i < OC * 72; i += 256) s_w2[i] = g_qw2[i];
    load_row_full(s_a + 0 * RSTRIDE, xn, h0 - 1, w0, inv);
    load_row_full(s_a + 1 * RSTRIDE, xn, h0,     w0, inv);
    load_row_full(s_a + 2 * RSTRIDE, xn, h0 + 1, w0, inv);
    __syncthreads();

    // role constants
    const int g  = lane >> 2, tg = lane & 3;          // tensor role
    const int dq = tid - 128;                          // dp4a role id (tid>=128)
    const int pxl = dq & 63, ocb = (dq >> 6) * 16;     // dp4a px-local, oc base

    float bv[8];
    #pragma unroll
    for (int nt = 0; nt < 4; nt++) {
        bv[2 * nt]     = s_bias[nt * 8 + tg * 2];
        bv[2 * nt + 1] = s_bias[nt * 8 + tg * 2 + 1];
    }

    // loader constants (main: px 0..127, halves; extra: px 128/129 1ch)
    const int lpx = tid >> 1, lhalf = tid & 1;
    const int lw  = w0 - 1 + lpx;
    const bool lwv = ((unsigned)lw < (unsigned)Ww);
    const float* lptr = xn + (size_t)(lhalf * 16) * HW + (lwv ? lw : 0);
    const int epx = 128 + (tid >> 5), ech = tid & 31;  // used if tid<64
    const int ew  = w0 - 1 + epx;
    const bool ewv = ((unsigned)ew < (unsigned)Ww);

    #pragma unroll 1
    for (int i = 0; i < ROWS; i++) {
        // ---- phase A: issue fp32 loads for input row h0+i+2 ----------------
        float f[16];
        float fe = 0.f;
        const int rp = h0 + i + 2;
        const bool pf = (i <= ROWS - 2);
        const bool vr = pf && (rp < Hh);
        {
            const bool v = vr && lwv;
            const float* p = lptr + (size_t)(v ? rp : 0) * Ww;
            #pragma unroll
            for (int k = 0; k < 16; k++)
                f[k] = v ? __ldg(p + (size_t)k * HW) : 0.f;
        }
        if (tid < 64 && vr && ewv)
            fe = __ldg(xn + (size_t)ech * HW + (size_t)rp * Ww + ew);

        // ---- phase B: compute output row h0+i (ring bufs i,i+1,i+2 mod 4) --
        const int h = h0 + i;
        if (warp < 4) {
            // tensor path: px w0 .. w0+63
            int acc[4][4];
            #pragma unroll
            for (int nt = 0; nt < 4; nt++) {
                acc[nt][0] = 0; acc[nt][1] = 0; acc[nt][2] = 0; acc[nt][3] = 0;
            }
            const uint32_t* wslot = &s_w[(g * 4 + tg) * 12];
            #pragma unroll
            for (int t = 0; t < 9; t++) {
                const int dh = t / 3, dw = t % 3;
                const char* ap = s_a + ((i + dh) & 3) * RSTRIDE
                               + (warp * 16 + g + dw) * 32 + tg * 4;
                uint32_t a0 = *(const uint32_t*)ap;
                uint32_t a2 = *(const uint32_t*)(ap + 16);
                uint32_t a1 = *(const uint32_t*)(ap + 256);   // px g+8
                uint32_t a3 = *(const uint32_t*)(ap + 272);
                const uint4* bp = (const uint4*)(wslot + t * (8 * 4 * 12));
                uint4 b0 = bp[0];
                uint4 b1 = bp[1];
                mma_s8(acc[0], a0, a1, a2, a3, b0.x, b1.x);
                mma_s8(acc[1], a0, a1, a2, a3, b0.y, b1.y);
                mma_s8(acc[2], a0, a1, a2, a3, b0.z, b1.z);
                mma_s8(acc[3], a0, a1, a2, a3, b0.w, b1.w);
            }
            float* ob = out + (size_t)n * OC * HW + (size_t)h * Ww
                      + (w0 + warp * 16);
            #pragma unroll
            for (int nt = 0; nt < 4; nt++) {
                int oc0 = nt * 8 + tg * 2;
                float* p0 = ob + (size_t)oc0 * HW;
                float* p1 = p0 + HW;
                p0[g]     = (float)acc[nt][0] * sc + bv[2 * nt];
                p1[g]     = (float)acc[nt][1] * sc + bv[2 * nt + 1];
                p0[g + 8] = (float)acc[nt][2] * sc + bv[2 * nt];
                p1[g + 8] = (float)acc[nt][3] * sc + bv[2 * nt + 1];
            }
        } else {
            // dp4a path: px w0+64 .. w0+127, 16 oc per thread
            int acc[16];
            #pragma unroll
            for (int o = 0; o < 16; o++) acc[o] = 0;
            #pragma unroll 1
            for (int t = 0; t < 9; t++) {
                const int dh = t / 3, dw = t % 3;
                const char* ap = s_a + ((i + dh) & 3) * RSTRIDE
                               + (64 + pxl + dw) * 32;
                uint4 A0 = *(const uint4*)ap;
                uint4 A1 = *(const uint4*)(ap + 16);
                const uint32_t* wp = &s_w2[ocb * 72 + t * 8];
                #pragma unroll
                for (int o = 0; o < 16; o++) {
                    const uint32_t* ww = wp + o * 72;
                    int s = acc[o];
                    s = __dp4a((int)A0.x, (int)ww[0], s);
                    s = __dp4a((int)A0.y, (int)ww[1], s);
                    s = __dp4a((int)A0.z, (int)ww[2], s);
                    s = __dp4a((int)A0.w, (int)ww[3], s);
                    s = __dp4a((int)A1.x, (int)ww[4], s);
                    s = __dp4a((int)A1.y, (int)ww[5], s);
                    s = __dp4a((int)A1.z, (int)ww[6], s);
                    s = __dp4a((int)A1.w, (int)ww[7], s);
                    acc[o] = s;
                }
            }
            float* op = out + (size_t)n * OC * HW + (size_t)ocb * HW
                      + (size_t)h * Ww + (w0 + 64 + pxl);
            #pragma unroll
            for (int o = 0; o < 16; o++)
                op[(size_t)o * HW] = (float)acc[o] * sc + s_bias[ocb + o];
        }

        // ---- phase D: quant + store row rp into buf (i+3)&3 ----------------
        if (pf) {
            char* dst = s_a + ((i + 3) & 3) * RSTRIDE;
            uint32_t wd[4];
            #pragma unroll
            for (int q4 = 0; q4 < 4; q4++) {
                uint32_t pw = 0;
                #pragma unroll
                for (int b = 0; b < 4; b++) {
                    int q = max(-127, min(127, __float2int_rn(f[q4 * 4 + b] * inv)));
                    pw |= (uint32_t)(q & 0xFF) << (8 * b);
                }
                wd[q4] = pw;
            }
            *(uint4*)(dst + lpx * 32 + lhalf * 16) =
                make_uint4(wd[0], wd[1], wd[2], wd[3]);
            if (tid < 64) {
                int q = max(-127, min(127, __float2int_rn(fe * inv)));
                *(int8_t*)(dst + epx * 32 + ech) = (int8_t)q;
            }
        }
        __syncthreads();
    }
}

// ---------------- launch ------------------------------------------------------
extern "C" void kernel_launch(void* const* d_in, const int* in_sizes, int n_in,
                              void* d_out, int out_size) {
    const float* x    = (const float*)d_in[0];
    const float* wgt  = (const float*)d_in[1];
    const float* bias = (const float*)d_in[2];
    float* out        = (float*)d_out;

    const int n4 = (Nn * Cc * HW) / 4; // 16,777,216 float4
    k_absmax<<<2048, 256>>>((const float4*)x, wgt, n4);

    dim3 grid(Ww / 128, Hh / ROWS, Nn); // (4, 32, 8)
    k_conv<<<grid, 256>>>(x, out, bias);
}

// round 12
// speedup vs baseline: 1.1070x; 1.1070x over previous
#include <cuda_runtime.h>
#include <cstdint>

// Problem shape (fixed by the dataset)
#define Nn 8
#define Cc 32
#define Hh 512
#define Ww 512
#define HW (Hh * Ww)          // 262144
#define OC 32

// ---------------- device scratch (allocation-free rule) ----------------------
__device__ float    g_blockmax[2048];   // per-block |x| maxima
__device__ float    g_sw;               // weight absmax
__device__ unsigned g_tile_ctr;         // dynamic tile ticket (reset in k_absmax)
// g_qw word order (R7-proven): i -> slot=i>>3 (slot=(t*8+g)*4+tg), j=i&7
//   (half=j>>2, nt=j&3); word packs ic=(tg+half*4)*4..+3 for oc=nt*8+g, tap t.
__device__ uint32_t g_qw[9 * 8 * 4 * 8]; // 9216 B

// ---------------- kernel 1: x per-block absmax (+ weight prep in block 0) ----
__global__ void k_absmax(const float4* __restrict__ x, const float* __restrict__ w,
                         int n4) {
    __shared__ float sred[8];
    float m = 0.f;
    for (int i = blockIdx.x * blockDim.x + threadIdx.x; i < n4;
         i += gridDim.x * blockDim.x) {
        float4 v = x[i];
        m = fmaxf(m, fmaxf(fmaxf(fabsf(v.x), fabsf(v.y)),
                           fmaxf(fabsf(v.z), fabsf(v.w))));
    }
    #pragma unroll
    for (int o = 16; o; o >>= 1) m = fmaxf(m, __shfl_xor_sync(~0u, m, o));
    if ((threadIdx.x & 31) == 0) sred[threadIdx.x >> 5] = m;
    __syncthreads();
    if (threadIdx.x == 0) {
        float v = sred[0];
        #pragma unroll
        for (int j = 1; j < 8; j++) v = fmaxf(v, sred[j]);
        g_blockmax[blockIdx.x] = v;
    }

    if (blockIdx.x == 0) {   // weight absmax + quantize + pre-shuffle
        if (threadIdx.x == 0) g_tile_ctr = 0u;   // reset ticket for k_conv
        __syncthreads();
        float mw = 0.f;
        for (int i = threadIdx.x; i < 9216; i += 256) mw = fmaxf(mw, fabsf(w[i]));
        #pragma unroll
        for (int o = 16; o; o >>= 1) mw = fmaxf(mw, __shfl_xor_sync(~0u, mw, o));
        if ((threadIdx.x & 31) == 0) sred[threadIdx.x >> 5] = mw;
        __syncthreads();
        __shared__ float s_sw;
        if (threadIdx.x == 0) {
            float v = sred[0];
            #pragma unroll
            for (int j = 1; j < 8; j++) v = fmaxf(v, sred[j]);
            s_sw = v;
            g_sw = v;
        }
        __syncthreads();
        float inv = 127.f / s_sw;
        for (int i = threadIdx.x; i < 9 * 8 * 4 * 8; i += 256) {
            int slot = i >> 3, j = i & 7;
            int tg = slot & 3, g = (slot >> 2) & 7, t = slot >> 5;
            int nt = j & 3, half = j >> 2;
            int oc  = nt * 8 + g;
            int ic0 = (tg + half * 4) * 4;
            uint32_t p = 0;
            #pragma unroll
            for (int b = 0; b < 4; b++) {
                int q = __float2int_rn(w[(oc * Cc + ic0 + b) * 9 + t] * inv);
                q = max(-127, min(127, q));
                p |= (uint32_t)(q & 0xFF) << (8 * b);
            }
            g_qw[i] = p;
        }
    }
}

// ---------------- kernel 2: fused quantize + int8 3x3 conv (IMMA) ------------
// Persistent-ish: 592 CTAs (4/SM x 148) pull 4-row x 128-px tiles off a
// global atomic ticket -> ~99% fill (R9's fixed grid filled only 86.5%).
// Per tile: 3-row quantized prologue into a 4-deep smem ring, then 4 output
// rows exactly as R9 (IMMA m16n8k32, fused dequant+bias epilogue).

__device__ __forceinline__ void mma_s8(int* c,
                                       uint32_t a0, uint32_t a1, uint32_t a2, uint32_t a3,
                                       uint32_t b0, uint32_t b1) {
    asm volatile(
        "mma.sync.aligned.m16n8k32.row.col.s32.s8.s8.s32 "
        "{%0,%1,%2,%3}, {%4,%5,%6,%7}, {%8,%9}, {%0,%1,%2,%3};\n"
        : "+r"(c[0]), "+r"(c[1]), "+r"(c[2]), "+r"(c[3])
        : "r"(a0), "r"(a1), "r"(a2), "r"(a3), "r"(b0), "r"(b1));
}

#define ROWS 4
#define NTILES (Nn * (Hh / ROWS) * (Ww / 128))   // 8 * 128 * 4 = 4096
#define NCTA 592
#define RSTRIDE 4224   // 132 px * 32 B

// Full (load+quant+store) row fill for the per-tile prologue.
// Ring buf holds input row r: px 1..128 = w0..w0+127; px 0 / 129 = halo cols.
__device__ __forceinline__ void load_row_full(char* dst, const float* __restrict__ xn,
                                              int r, int w0, float inv) {
    const int tid = threadIdx.x;
    const int pxm = (tid & 127) + 1, hf = tid >> 7;
    const bool vr = ((unsigned)r < (unsigned)Hh);
    const float* p = xn + (size_t)(hf * 16) * HW + (size_t)(vr ? r : 0) * Ww
                   + (w0 + (tid & 127));
    uint32_t wd[4];
    #pragma unroll
    for (int q4 = 0; q4 < 4; q4++) {
        uint32_t pw = 0;
        #pragma unroll
        for (int b = 0; b < 4; b++) {
            float v = vr ? __ldg(p + (size_t)(q4 * 4 + b) * HW) : 0.f;
            int q = max(-127, min(127, __float2int_rn(v * inv)));
            pw |= (uint32_t)(q & 0xFF) << (8 * b);
        }
        wd[q4] = pw;
    }
    *(uint4*)(dst + pxm * 32 + hf * 16) = make_uint4(wd[0], wd[1], wd[2], wd[3]);
    if (tid < 64) {   // 2 halo columns x 32 ch
        int hp = (tid < 32) ? 0 : 129;
        int wh = w0 - 1 + hp;
        int ch = tid & 31;
        float v = 0.f;
        if (vr && wh >= 0 && wh < Ww)
            v = __ldg(xn + (size_t)ch * HW + (size_t)r * Ww + wh);
        int q = max(-127, min(127, __float2int_rn(v * inv)));
        *(int8_t*)(dst + hp * 32 + ch) = (int8_t)q;
    }
}

__global__ void __launch_bounds__(256, 4) k_conv(const float* __restrict__ x,
                                                 float* __restrict__ out,
                                                 const float* __restrict__ bias) {
    __shared__ uint32_t s_w[9 * 8 * 4 * 12];  // 13824 B, 48B slot stride
    __shared__ char     s_a[4 * RSTRIDE];     // 16896 B ring
    __shared__ float    s_red[8];
    __shared__ float    s_scale, s_inv;
    __shared__ unsigned s_tile;

    const int tid  = threadIdx.x;
    const int warp = tid >> 5, lane = tid & 31;
    const int g    = lane >> 2, tg = lane & 3;

    // one-time CTA init: final absmax, weights, bias fragments
    {
        float m = 0.f;
        for (int j = tid; j < 2048; j += 256) m = fmaxf(m, g_blockmax[j]);
        #pragma unroll
        for (int o = 16; o; o >>= 1) m = fmaxf(m, __shfl_xor_sync(~0u, m, o));
        if (lane == 0) s_red[warp] = m;
    }
    __syncthreads();
    if (tid == 0) {
        float v = s_red[0];
        #pragma unroll
        for (int j = 1; j < 8; j++) v = fmaxf(v, s_red[j]);
        s_scale = v * g_sw * (1.f / 16129.f);
        s_inv   = 127.f / v;
    }
    for (int i = tid; i < 9 * 8 * 4 * 8; i += 256)
        s_w[(i >> 3) * 12 + (i & 7)] = g_qw[i];
    __syncthreads();
    const float inv = s_inv, sc = s_scale;

    float bv[8];
    #pragma unroll
    for (int nt = 0; nt < 4; nt++) {
        bv[2 * nt]     = __ldg(bias + nt * 8 + tg * 2);
        bv[2 * nt + 1] = __ldg(bias + nt * 8 + tg * 2 + 1);
    }

    const int pxm = (tid & 127) + 1, hf = tid >> 7;
    const int hp = (tid < 32) ? 0 : 129;
    const uint32_t* wslot = &s_w[(g * 4 + tg) * 12];

    for (;;) {
        // ---- grab next tile ------------------------------------------------
        if (tid == 0) s_tile = atomicAdd(&g_tile_ctr, 1u);
        __syncthreads();
        const unsigned t5 = s_tile;
        if (t5 >= NTILES) break;
        const int w0 = (int)(t5 & 3) * 128;
        const int h0 = (int)((t5 >> 2) & 127) * ROWS;
        const int n  = (int)(t5 >> 9);
        const float* xn = x + (size_t)n * Cc * HW;

        // tile-local loader constants
        const float* pmain = xn + (size_t)(hf * 16) * HW + (w0 + (tid & 127));
        const int wh  = w0 - 1 + hp;
        const bool whv = (wh >= 0) && (wh < Ww);

        // prologue rows h0-1, h0, h0+1 -> bufs 0,1,2
        load_row_full(s_a + 0 * RSTRIDE, xn, h0 - 1, w0, inv);
        load_row_full(s_a + 1 * RSTRIDE, xn, h0,     w0, inv);
        load_row_full(s_a + 2 * RSTRIDE, xn, h0 + 1, w0, inv);
        __syncthreads();

        #pragma unroll 1
        for (int i = 0; i < ROWS; i++) {
            // ---- phase A: issue fp32 loads for input row h0+i+2 ------------
            float f[16];
            float fhalo = 0.f;
            const int rp = h0 + i + 2;
            const bool pf = (i <= ROWS - 2);
            const bool vr = pf && (rp < Hh);
            #pragma unroll
            for (int k = 0; k < 16; k++)
                f[k] = vr ? __ldg(pmain + (size_t)rp * Ww + (size_t)k * HW) : 0.f;
            if (tid < 64 && vr && whv)
                fhalo = __ldg(xn + (size_t)(tid & 31) * HW + (size_t)rp * Ww + wh);

            // ---- phase B: MMA for output row h0+i (bufs i,i+1,i+2 mod 4) ---
            int acc[4][4];
            #pragma unroll
            for (int nt = 0; nt < 4; nt++) {
                acc[nt][0] = 0; acc[nt][1] = 0; acc[nt][2] = 0; acc[nt][3] = 0;
            }
            #pragma unroll
            for (int t = 0; t < 9; t++) {
                const int dh = t / 3, dw = t % 3;
                const char* ap = s_a + ((i + dh) & 3) * RSTRIDE
                               + (warp * 16 + g + dw) * 32 + tg * 4;
                uint32_t a0 = *(const uint32_t*)ap;
                uint32_t a2 = *(const uint32_t*)(ap + 16);
                uint32_t a1 = *(const uint32_t*)(ap + 256);   // pixel g+8
                uint32_t a3 = *(const uint32_t*)(ap + 272);
                const uint4* bp = (const uint4*)(wslot + t * (8 * 4 * 12));
                uint4 b0 = bp[0];
                uint4 b1 = bp[1];
                mma_s8(acc[0], a0, a1, a2, a3, b0.x, b1.x);
                mma_s8(acc[1], a0, a1, a2, a3, b0.y, b1.y);
                mma_s8(acc[2], a0, a1, a2, a3, b0.z, b1.z);
                mma_s8(acc[3], a0, a1, a2, a3, b0.w, b1.w);
            }
            // epilogue: C m16n8 -> NCHW fp32
            {
                const int h = h0 + i;
                float* ob = out + (size_t)n * OC * HW + (size_t)h * Ww
                          + (w0 + warp * 16);
                #pragma unroll
                for (int nt = 0; nt < 4; nt++) {
                    int oc0 = nt * 8 + tg * 2;
                    float* p0 = ob + (size_t)oc0 * HW;
                    float* p1 = p0 + HW;
                    p0[g]     = (float)acc[nt][0] * sc + bv[2 * nt];
                    p1[g]     = (float)acc[nt][1] * sc + bv[2 * nt + 1];
                    p0[g + 8] = (float)acc[nt][2] * sc + bv[2 * nt];
                    p1[g + 8] = (float)acc[nt][3] * sc + bv[2 * nt + 1];
                }
            }

            // ---- phase D: quantize + store row rp into buf (i+3)&3 ---------
            if (pf) {
                char* dst = s_a + ((i + 3) & 3) * RSTRIDE;
                uint32_t wd[4];
                #pragma unroll
                for (int q4 = 0; q4 < 4; q4++) {
                    uint32_t pw = 0;
                    #pragma unroll
                    for (int b = 0; b < 4; b++) {
                        int q = max(-127, min(127, __float2int_rn(f[q4 * 4 + b] * inv)));
                        pw |= (uint32_t)(q & 0xFF) << (8 * b);
                    }
                    wd[q4] = pw;
                }
                *(uint4*)(dst + pxm * 32 + hf * 16) =
                    make_uint4(wd[0], wd[1], wd[2], wd[3]);
                if (tid < 64) {
                    int q = max(-127, min(127, __float2int_rn(fhalo * inv)));
                    *(int8_t*)(dst + hp * 32 + (tid & 31)) = (int8_t)q;
                }
            }
            __syncthreads();
        }
    }
}

// ---------------- launch ------------------------------------------------------
extern "C" void kernel_launch(void* const* d_in, const int* in_sizes, int n_in,
                              void* d_out, int out_size) {
    const float* x    = (const float*)d_in[0];
    const float* wgt  = (const float*)d_in[1];
    const float* bias = (const float*)d_in[2];
    float* out        = (float*)d_out;

    const int n4 = (Nn * Cc * HW) / 4; // 16,777,216 float4
    k_absmax<<<2048, 256>>>((const float4*)x, wgt, n4);

    k_conv<<<NCTA, 256>>>(x, out, bias);
}

// round 14
// speedup vs baseline: 1.2572x; 1.1357x over previous
#include <cuda_runtime.h>
#include <cstdint>

// Problem shape (fixed by the dataset)
#define Nn 8
#define Cc 32
#define Hh 512
#define Ww 512
#define HW (Hh * Ww)          // 262144
#define OC 32

// ---------------- device scratch (allocation-free rule) ----------------------
__device__ float    g_blockmax[2048];   // per-block |x| maxima
__device__ float    g_sw;               // weight absmax
__device__ unsigned g_tile_ctr;         // dynamic tile ticket (reset in k_absmax)
// Tensor layout (R7-proven): i -> slot=i>>3 (slot=(t*8+g)*4+tg), j=i&7
//   (half=j>>2, nt=j&3); word packs ic=(tg+half*4)*4..+3 for oc=nt*8+g, tap t.
__device__ uint32_t g_qw[9 * 8 * 4 * 8];   // 9216 B
// dp4a layout (R5-proven): word[oc*72 + t*8 + j] packs ic j*4..+3.
__device__ uint32_t g_qw2[OC * 72];        // 9216 B

// ---------------- kernel 1: x per-block absmax (+ weight prep in block 0) ----
__global__ void k_absmax(const float4* __restrict__ x, const float* __restrict__ w,
                         int n4) {
    __shared__ float sred[8];
    float m = 0.f;
    for (int i = blockIdx.x * blockDim.x + threadIdx.x; i < n4;
         i += gridDim.x * blockDim.x) {
        float4 v = x[i];
        m = fmaxf(m, fmaxf(fmaxf(fabsf(v.x), fabsf(v.y)),
                           fmaxf(fabsf(v.z), fabsf(v.w))));
    }
    #pragma unroll
    for (int o = 16; o; o >>= 1) m = fmaxf(m, __shfl_xor_sync(~0u, m, o));
    if ((threadIdx.x & 31) == 0) sred[threadIdx.x >> 5] = m;
    __syncthreads();
    if (threadIdx.x == 0) {
        float v = sred[0];
        #pragma unroll
        for (int j = 1; j < 8; j++) v = fmaxf(v, sred[j]);
        g_blockmax[blockIdx.x] = v;
    }

    if (blockIdx.x == 0) {   // weight absmax + quantize into both layouts
        if (threadIdx.x == 0) g_tile_ctr = 0u;   // reset ticket for k_conv
        __syncthreads();
        float mw = 0.f;
        for (int i = threadIdx.x; i < 9216; i += 256) mw = fmaxf(mw, fabsf(w[i]));
        #pragma unroll
        for (int o = 16; o; o >>= 1) mw = fmaxf(mw, __shfl_xor_sync(~0u, mw, o));
        if ((threadIdx.x & 31) == 0) sred[threadIdx.x >> 5] = mw;
        __syncthreads();
        __shared__ float s_sw;
        if (threadIdx.x == 0) {
            float v = sred[0];
            #pragma unroll
            for (int j = 1; j < 8; j++) v = fmaxf(v, sred[j]);
            s_sw = v;
            g_sw = v;
        }
        __syncthreads();
        float inv = 127.f / s_sw;
        for (int i = threadIdx.x; i < 9 * 8 * 4 * 8; i += 256) {   // tensor layout
            int slot = i >> 3, j = i & 7;
            int tg = slot & 3, g = (slot >> 2) & 7, t = slot >> 5;
            int nt = j & 3, half = j >> 2;
            int oc  = nt * 8 + g;
            int ic0 = (tg + half * 4) * 4;
            uint32_t p = 0;
            #pragma unroll
            for (int b = 0; b < 4; b++) {
                int q = __float2int_rn(w[(oc * Cc + ic0 + b) * 9 + t] * inv);
                q = max(-127, min(127, q));
                p |= (uint32_t)(q & 0xFF) << (8 * b);
            }
            g_qw[i] = p;
        }
        for (int i = threadIdx.x; i < OC * 72; i += 256) {         // dp4a layout
            int oc = i / 72, rem = i % 72, t = rem >> 3, j = rem & 7;
            int ic0 = j * 4;
            uint32_t p = 0;
            #pragma unroll
            for (int b = 0; b < 4; b++) {
                int q = __float2int_rn(w[(oc * Cc + ic0 + b) * 9 + t] * inv);
                q = max(-127, min(127, q));
                p |= (uint32_t)(q & 0xFF) << (8 * b);
            }
            g_qw2[i] = p;
        }
    }
}

// ---------------- kernel 2: fused quantize + DUAL-PIPE int8 conv -------------
// 592 CTAs, role by (bid/148)&1: alternating placement waves -> each SM hosts
// tensor-CTAs AND dp4a-CTAs concurrently (independent math pipes). All CTAs
// pull 4-row x 128-px tiles from one atomic ticket (auto load balance).

__device__ __forceinline__ void mma_s8(int* c,
                                       uint32_t a0, uint32_t a1, uint32_t a2, uint32_t a3,
                                       uint32_t b0, uint32_t b1) {
    asm volatile(
        "mma.sync.aligned.m16n8k32.row.col.s32.s8.s8.s32 "
        "{%0,%1,%2,%3}, {%4,%5,%6,%7}, {%8,%9}, {%0,%1,%2,%3};\n"
        : "+r"(c[0]), "+r"(c[1]), "+r"(c[2]), "+r"(c[3])
        : "r"(a0), "r"(a1), "r"(a2), "r"(a3), "r"(b0), "r"(b1));
}

#define ROWS 4
#define NTILES (Nn * (Hh / ROWS) * (Ww / 128))   // 4096
#define NCTA 592
#define RSTRIDE 4224   // 132 px * 32 B

// Prologue row fill (load+quant+store). Ring px p <-> input w = w0-1+p.
__device__ __forceinline__ void load_row_full(char* dst, const float* __restrict__ xn,
                                              int r, int w0, float inv) {
    const int tid = threadIdx.x;
    const int pxm = (tid & 127) + 1, hf = tid >> 7;
    const bool vr = ((unsigned)r < (unsigned)Hh);
    const float* p = xn + (size_t)(hf * 16) * HW + (size_t)(vr ? r : 0) * Ww
                   + (w0 + (tid & 127));
    uint32_t wd[4];
    #pragma unroll
    for (int q4 = 0; q4 < 4; q4++) {
        uint32_t pw = 0;
        #pragma unroll
        for (int b = 0; b < 4; b++) {
            float v = vr ? __ldg(p + (size_t)(q4 * 4 + b) * HW) : 0.f;
            int q = max(-127, min(127, __float2int_rn(v * inv)));
            pw |= (uint32_t)(q & 0xFF) << (8 * b);
        }
        wd[q4] = pw;
    }
    *(uint4*)(dst + pxm * 32 + hf * 16) = make_uint4(wd[0], wd[1], wd[2], wd[3]);
    if (tid < 64) {   // halo px 0 / 129, one channel per thread
        int hp = (tid < 32) ? 0 : 129;
        int wh = w0 - 1 + hp;
        int ch = tid & 31;
        float v = 0.f;
        if (vr && wh >= 0 && wh < Ww)
            v = __ldg(xn + (size_t)ch * HW + (size_t)r * Ww + wh);
        int q = max(-127, min(127, __float2int_rn(v * inv)));
        *(int8_t*)(dst + hp * 32 + ch) = (int8_t)q;
    }
}

__global__ void __launch_bounds__(256, 4) k_conv(const float* __restrict__ x,
                                                 float* __restrict__ out,
                                                 const float* __restrict__ bias) {
    __shared__ uint32_t s_w[9 * 8 * 4 * 12];  // 13824 B (union: both layouts)
    __shared__ char     s_a[4 * RSTRIDE];     // 16896 B ring
    __shared__ float    s_red[8];
    __shared__ float    s_bias[OC];
    __shared__ float    s_scale, s_inv;
    __shared__ unsigned s_tile;

    const int tid  = threadIdx.x;
    const int warp = tid >> 5, lane = tid & 31;
    const int role = (blockIdx.x / 148) & 1;   // 0 = tensor, 1 = dp4a

    // one-time init: final absmax, weights (role layout), bias
    {
        float m = 0.f;
        for (int j = tid; j < 2048; j += 256) m = fmaxf(m, g_blockmax[j]);
        #pragma unroll
        for (int o = 16; o; o >>= 1) m = fmaxf(m, __shfl_xor_sync(~0u, m, o));
        if (lane == 0) s_red[warp] = m;
    }
    if (tid < 32) s_bias[tid] = __ldg(bias + tid);
    __syncthreads();
    if (tid == 0) {
        float v = s_red[0];
        #pragma unroll
        for (int j = 1; j < 8; j++) v = fmaxf(v, s_red[j]);
        s_scale = v * g_sw * (1.f / 16129.f);
        s_inv   = 127.f / v;
    }
    if (role == 0) {
        for (int i = tid; i < 9 * 8 * 4 * 8; i += 256)
            s_w[(i >> 3) * 12 + (i & 7)] = g_qw[i];
    } else {
        for (int i = tid; i < OC * 72; i += 256) s_w[i] = g_qw2[i];
    }
    __syncthreads();
    const float inv = s_inv, sc = s_scale;

    // role constants
    const int g  = lane >> 2, tg = lane & 3;            // tensor
    const int dpx = tid & 127, ocb = (tid >> 7) * 16;   // dp4a: px, oc base
    float bv[8];
    #pragma unroll
    for (int nt = 0; nt < 4; nt++) {
        bv[2 * nt]     = s_bias[nt * 8 + tg * 2];
        bv[2 * nt + 1] = s_bias[nt * 8 + tg * 2 + 1];
    }
    const int pxm = (tid & 127) + 1, hf = tid >> 7;
    const int hp = (tid < 32) ? 0 : 129;
    const uint32_t* wslot = &s_w[(g * 4 + tg) * 12];

    for (;;) {
        if (tid == 0) s_tile = atomicAdd(&g_tile_ctr, 1u);
        __syncthreads();
        const unsigned t5 = s_tile;
        if (t5 >= NTILES) break;
        const int w0 = (int)(t5 & 3) * 128;
        const int h0 = (int)((t5 >> 2) & 127) * ROWS;
        const int n  = (int)(t5 >> 9);
        const float* xn = x + (size_t)n * Cc * HW;

        const float* pmain = xn + (size_t)(hf * 16) * HW + (w0 + (tid & 127));
        const int wh  = w0 - 1 + hp;
        const bool whv = (wh >= 0) && (wh < Ww);

        load_row_full(s_a + 0 * RSTRIDE, xn, h0 - 1, w0, inv);
        load_row_full(s_a + 1 * RSTRIDE, xn, h0,     w0, inv);
        load_row_full(s_a + 2 * RSTRIDE, xn, h0 + 1, w0, inv);
        __syncthreads();

        #pragma unroll 1
        for (int i = 0; i < ROWS; i++) {
            // ---- phase A: issue fp32 loads for input row h0+i+2 ------------
            float f[16];
            float fhalo = 0.f;
            const int rp = h0 + i + 2;
            const bool pf = (i <= ROWS - 2);
            const bool vr = pf && (rp < Hh);
            #pragma unroll
            for (int k = 0; k < 16; k++)
                f[k] = vr ? __ldg(pmain + (size_t)rp * Ww + (size_t)k * HW) : 0.f;
            if (tid < 64 && vr && whv)
                fhalo = __ldg(xn + (size_t)(tid & 31) * HW + (size_t)rp * Ww + wh);

            // ---- phase B: compute output row h0+i --------------------------
            const int h = h0 + i;
            if (role == 0) {
                // tensor path (R12-identical)
                int acc[4][4];
                #pragma unroll
                for (int nt = 0; nt < 4; nt++) {
                    acc[nt][0] = 0; acc[nt][1] = 0; acc[nt][2] = 0; acc[nt][3] = 0;
                }
                #pragma unroll
                for (int t = 0; t < 9; t++) {
                    const int dh = t / 3, dw = t % 3;
                    const char* ap = s_a + ((i + dh) & 3) * RSTRIDE
                                   + (warp * 16 + g + dw) * 32 + tg * 4;
                    uint32_t a0 = *(const uint32_t*)ap;
                    uint32_t a2 = *(const uint32_t*)(ap + 16);
                    uint32_t a1 = *(const uint32_t*)(ap + 256);
                    uint32_t a3 = *(const uint32_t*)(ap + 272);
                    const uint4* bp = (const uint4*)(wslot + t * (8 * 4 * 12));
                    uint4 b0 = bp[0];
                    uint4 b1 = bp[1];
                    mma_s8(acc[0], a0, a1, a2, a3, b0.x, b1.x);
                    mma_s8(acc[1], a0, a1, a2, a3, b0.y, b1.y);
                    mma_s8(acc[2], a0, a1, a2, a3, b0.z, b1.z);
                    mma_s8(acc[3], a0, a1, a2, a3, b0.w, b1.w);
                }
                float* ob = out + (size_t)n * OC * HW + (size_t)h * Ww
                          + (w0 + warp * 16);
                #pragma unroll
                for (int nt = 0; nt < 4; nt++) {
                    int oc0 = nt * 8 + tg * 2;
                    float* p0 = ob + (size_t)oc0 * HW;
                    float* p1 = p0 + HW;
                    p0[g]     = (float)acc[nt][0] * sc + bv[2 * nt];
                    p1[g]     = (float)acc[nt][1] * sc + bv[2 * nt + 1];
                    p0[g + 8] = (float)acc[nt][2] * sc + bv[2 * nt];
                    p1[g + 8] = (float)acc[nt][3] * sc + bv[2 * nt + 1];
                }
            } else {
                // dp4a path: thread = 1 px x 16 oc (R5-proven inner loop)
                int acc[16];
                #pragma unroll
                for (int o = 0; o < 16; o++) acc[o] = 0;
                #pragma unroll 1
                for (int t = 0; t < 9; t++) {
                    const int dh = t / 3, dw = t % 3;
                    const char* ap = s_a + ((i + dh) & 3) * RSTRIDE
                                   + (dpx + dw) * 32;
                    uint4 A0 = *(const uint4*)ap;
                    uint4 A1 = *(const uint4*)(ap + 16);
                    const uint32_t* wp = &s_w[ocb * 72 + t * 8];
                    #pragma unroll
                    for (int o = 0; o < 16; o++) {
                        const uint32_t* ww = wp + o * 72;
                        int s = acc[o];
                        s = __dp4a((int)A0.x, (int)ww[0], s);
                        s = __dp4a((int)A0.y, (int)ww[1], s);
                        s = __dp4a((int)A0.z, (int)ww[2], s);
                        s = __dp4a((int)A0.w, (int)ww[3], s);
                        s = __dp4a((int)A1.x, (int)ww[4], s);
                        s = __dp4a((int)A1.y, (int)ww[5], s);
                        s = __dp4a((int)A1.z, (int)ww[6], s);
                        s = __dp4a((int)A1.w, (int)ww[7], s);
                        acc[o] = s;
                    }
                }
                float* op = out + (size_t)n * OC * HW + (size_t)ocb * HW
                          + (size_t)h * Ww + (w0 + dpx);
                #pragma unroll
                for (int o = 0; o < 16; o++)
                    op[(size_t)o * HW] = (float)acc[o] * sc + s_bias[ocb + o];
            }

            // ---- phase D: quantize + store row rp into buf (i+3)&3 ---------
            if (pf) {
                char* dst = s_a + ((i + 3) & 3) * RSTRIDE;
                uint32_t wd[4];
                #pragma unroll
                for (int q4 = 0; q4 < 4; q4++) {
                    uint32_t pw = 0;
                    #pragma unroll
                    for (int b = 0; b < 4; b++) {
                        int q = max(-127, min(127, __float2int_rn(f[q4 * 4 + b] * inv)));
                        pw |= (uint32_t)(q & 0xFF) << (8 * b);
                    }
                    wd[q4] = pw;
                }
                *(uint4*)(dst + pxm * 32 + hf * 16) =
                    make_uint4(wd[0], wd[1], wd[2], wd[3]);
                if (tid < 64) {
                    int q = max(-127, min(127, __float2int_rn(fhalo * inv)));
                    *(int8_t*)(dst + hp * 32 + (tid & 31)) = (int8_t)q;
                }
            }
            __syncthreads();
        }
    }
}

// ---------------- launch ------------------------------------------------------
extern "C" void kernel_launch(void* const* d_in, const int* in_sizes, int n_in,
                              void* d_out, int out_size) {
    const float* x    = (const float*)d_in[0];
    const float* wgt  = (const float*)d_in[1];
    const float* bias = (const float*)d_in[2];
    float* out        = (float*)d_out;

    const int n4 = (Nn * Cc * HW) / 4; // 16,777,216 float4
    k_absmax<<<2048, 256>>>((const float4*)x, wgt, n4);

    k_conv<<<NCTA, 256>>>(x, out, bias);
}